// round 1
// baseline (speedup 1.0000x reference)
#include <cuda_runtime.h>
#include <math.h>

#define T_TOK 4096
#define D_MODEL 512
#define E_EXP 8
#define H_HID 1024
#define DFF_DIM 2048

// ---------------- scratch (static device globals; no allocation) --------------
__device__ __align__(16) float g_xin[T_TOK * D_MODEL];          // FiLM-modulated LN(x)
__device__ __align__(16) float g_xs[T_TOK * D_MODEL];           // pre-LN for shared FFN
__device__ __align__(16) float g_t1[T_TOK * DFF_DIM];           // shared FFN hidden
__device__ __align__(16) float g_sh[T_TOK * D_MODEL];           // shared FFN out
__device__ __align__(16) float g_h1[E_EXP * T_TOK * H_HID];     // expert hidden (capacity T per expert)
__device__ __align__(16) float g_moe2[T_TOK * 2 * D_MODEL];     // per (token,slot) expert output
__device__ int   g_cnt[E_EXP];
__device__ int   g_list[E_EXP * T_TOK];    // packed token*2 + slot
__device__ float g_glist[E_EXP * T_TOK];   // gate value

__device__ __forceinline__ float gelu_tanh(float x) {
    // matches jax.nn.gelu(approximate=True)
    float x3 = x * x * x;
    return 0.5f * x * (1.0f + tanhf(0.7978845608028654f * (x + 0.044715f * x3)));
}

// ---------------- counters reset (graph-replay safe) --------------------------
__global__ void zero_cnt_kernel() {
    if (threadIdx.x < E_EXP) g_cnt[threadIdx.x] = 0;
}

// ---------------- per-token prep: LN x2, feat, FiLM, router top-2 -------------
__global__ void prep_kernel(
    const float* __restrict__ hid, const float* __restrict__ raw,
    const float* __restrict__ ln_g, const float* __restrict__ ln_b,
    const float* __restrict__ pg,   const float* __restrict__ pb,
    const float* __restrict__ feat_w, const float* __restrict__ feat_b,
    const float* __restrict__ film_w, const float* __restrict__ film_b,
    const float* __restrict__ rw, const float* __restrict__ rb)
{
    int t = blockIdx.x;
    int tid = threadIdx.x;  // 256 threads

    __shared__ float red[256];
    __shared__ float s_x[D_MODEL];
    __shared__ float s_feat[64];
    __shared__ float s_logits[E_EXP];

    float h0 = hid[t * D_MODEL + tid];
    float h1 = hid[t * D_MODEL + 256 + tid];

    // mean
    red[tid] = h0 + h1;
    __syncthreads();
    #pragma unroll
    for (int s = 128; s > 0; s >>= 1) {
        if (tid < s) red[tid] += red[tid + s];
        __syncthreads();
    }
    float mean = red[0] * (1.0f / 512.0f);
    __syncthreads();

    // var
    float d0 = h0 - mean, d1 = h1 - mean;
    red[tid] = d0 * d0 + d1 * d1;
    __syncthreads();
    #pragma unroll
    for (int s = 128; s > 0; s >>= 1) {
        if (tid < s) red[tid] += red[tid + s];
        __syncthreads();
    }
    float inv = rsqrtf(red[0] * (1.0f / 512.0f) + 1e-5f);

    float x0 = d0 * inv, x1 = d1 * inv;
    s_x[tid]       = x0 * ln_g[tid]       + ln_b[tid];
    s_x[tid + 256] = x1 * ln_g[tid + 256] + ln_b[tid + 256];
    g_xs[t * D_MODEL + tid]       = x0 * pg[tid]       + pb[tid];
    g_xs[t * D_MODEL + tid + 256] = x1 * pg[tid + 256] + pb[tid + 256];

    // feature encoder: [16] @ [16,64]
    if (tid < 64) {
        float acc = feat_b[tid];
        #pragma unroll
        for (int i = 0; i < 16; i++) acc += raw[t * 16 + i] * feat_w[i * 64 + tid];
        s_feat[tid] = acc;
    }
    __syncthreads();

    // FiLM: [64] @ [64,1024] -> gamma(0:512), beta(512:1024); x_in = x*(1+g)+b
    #pragma unroll
    for (int r = 0; r < 2; r++) {
        int d = tid + r * 256;
        float gma = film_b[d];
        float bta = film_b[512 + d];
        #pragma unroll
        for (int i = 0; i < 64; i++) {
            float f = s_feat[i];
            gma += f * film_w[i * 1024 + d];
            bta += f * film_w[i * 1024 + 512 + d];
        }
        g_xin[t * D_MODEL + d] = s_x[d] * (1.0f + gma) + bta;
    }

    // router logits: warp w computes logit[w]  (router_w is [512,8] row-major)
    {
        int w = tid >> 5, lane = tid & 31;
        float acc = 0.0f;
        #pragma unroll
        for (int d = 0; d < 512; d += 32) acc += s_x[d + lane] * rw[(d + lane) * E_EXP + w];
        #pragma unroll
        for (int off = 16; off; off >>= 1) acc += __shfl_down_sync(0xffffffff, acc, off);
        if (lane == 0) s_logits[w] = acc + rb[w];   // TEMP = 1
    }
    __syncthreads();

    if (tid == 0) {
        int i0 = 0; float v0 = s_logits[0];
        #pragma unroll
        for (int e = 1; e < E_EXP; e++) { float v = s_logits[e]; if (v > v0) { v0 = v; i0 = e; } }
        int i1 = -1; float v1 = -1e30f;
        #pragma unroll
        for (int e = 0; e < E_EXP; e++) {
            if (e == i0) continue;
            float v = s_logits[e]; if (v > v1) { v1 = v; i1 = e; }
        }
        float b  = expf(v1 - v0);
        float g0 = 1.0f / (1.0f + b);
        float g1 = b * g0;
        int p0 = atomicAdd(&g_cnt[i0], 1);
        g_list[i0 * T_TOK + p0] = t * 2 + 0;  g_glist[i0 * T_TOK + p0] = g0;
        int p1 = atomicAdd(&g_cnt[i1], 1);
        g_list[i1 * T_TOK + p1] = t * 2 + 1;  g_glist[i1 * T_TOK + p1] = g1;
    }
}

// ---------------- tiled GEMM core (64x64x16, 256 thr, 4x4 per thread) ---------
#define GEMM_PROLOG()                                            \
    __shared__ float Ast[16][68];                                \
    __shared__ float Bs[16][64];                                 \
    int tid = threadIdx.x;                                       \
    int ar = tid >> 2, ac = (tid & 3) * 4;                       \
    int br = tid >> 4, bc = (tid & 15) * 4;                      \
    int tx = tid & 15, ty = tid >> 4;                            \
    float acc[4][4] = {};

#define GEMM_TILE(A4EXPR, BPTR, KDIM, NDIM)                                    \
    for (int k0 = 0; k0 < (KDIM); k0 += 16) {                                  \
        float4 a4 = (A4EXPR);                                                  \
        Ast[ac + 0][ar] = a4.x; Ast[ac + 1][ar] = a4.y;                        \
        Ast[ac + 2][ar] = a4.z; Ast[ac + 3][ar] = a4.w;                        \
        *(float4*)&Bs[br][bc] =                                                \
            *(const float4*)&(BPTR)[(size_t)(k0 + br) * (NDIM) + n0 + bc];     \
        __syncthreads();                                                       \
        _Pragma("unroll")                                                      \
        for (int kk = 0; kk < 16; kk++) {                                      \
            float4 a = *(float4*)&Ast[kk][ty * 4];                             \
            float4 b = *(float4*)&Bs[kk][tx * 4];                              \
            acc[0][0] += a.x * b.x; acc[0][1] += a.x * b.y;                    \
            acc[0][2] += a.x * b.z; acc[0][3] += a.x * b.w;                    \
            acc[1][0] += a.y * b.x; acc[1][1] += a.y * b.y;                    \
            acc[1][2] += a.y * b.z; acc[1][3] += a.y * b.w;                    \
            acc[2][0] += a.z * b.x; acc[2][1] += a.z * b.y;                    \
            acc[2][2] += a.z * b.z; acc[2][3] += a.z * b.w;                    \
            acc[3][0] += a.w * b.x; acc[3][1] += a.w * b.y;                    \
            acc[3][2] += a.w * b.z; acc[3][3] += a.w * b.w;                    \
        }                                                                      \
        __syncthreads();                                                       \
    }

// shared FFN GEMM1: g_t1 = gelu(g_xs @ fc1 + b)
__global__ void ffn_gemm1(const float* __restrict__ W, const float* __restrict__ bias) {
    int m0 = blockIdx.y * 64, n0 = blockIdx.x * 64;
    GEMM_PROLOG();
    GEMM_TILE((*(const float4*)&g_xs[(size_t)(m0 + ar) * D_MODEL + k0 + ac]), W, D_MODEL, DFF_DIM);
    #pragma unroll
    for (int i = 0; i < 4; i++) {
        int row = m0 + ty * 4 + i;
        int col = n0 + tx * 4;
        float4 o;
        o.x = gelu_tanh(acc[i][0] + bias[col + 0]);
        o.y = gelu_tanh(acc[i][1] + bias[col + 1]);
        o.z = gelu_tanh(acc[i][2] + bias[col + 2]);
        o.w = gelu_tanh(acc[i][3] + bias[col + 3]);
        *(float4*)&g_t1[(size_t)row * DFF_DIM + col] = o;
    }
}

// shared FFN GEMM2: g_sh = g_t1 @ fc2 + b
__global__ void ffn_gemm2(const float* __restrict__ W, const float* __restrict__ bias) {
    int m0 = blockIdx.y * 64, n0 = blockIdx.x * 64;
    GEMM_PROLOG();
    GEMM_TILE((*(const float4*)&g_t1[(size_t)(m0 + ar) * DFF_DIM + k0 + ac]), W, DFF_DIM, D_MODEL);
    #pragma unroll
    for (int i = 0; i < 4; i++) {
        int row = m0 + ty * 4 + i;
        int col = n0 + tx * 4;
        float4 o;
        o.x = acc[i][0] + bias[col + 0];
        o.y = acc[i][1] + bias[col + 1];
        o.z = acc[i][2] + bias[col + 2];
        o.w = acc[i][3] + bias[col + 3];
        *(float4*)&g_sh[(size_t)row * D_MODEL + col] = o;
    }
}

// MoE GEMM1 (gathered): g_h1[e][i] = gelu(x_in[list[e][i]] @ w1[e] + b1[e])
__global__ void moe_gemm1(const float* __restrict__ w1, const float* __restrict__ b1) {
    int e = blockIdx.z;
    int M = g_cnt[e];
    int m0 = blockIdx.y * 64;
    if (m0 >= M) return;
    int n0 = blockIdx.x * 64;
    const float* W = w1 + (size_t)e * D_MODEL * H_HID;
    GEMM_PROLOG();
    int row_i = m0 + ar;
    int tok = (row_i < M) ? (g_list[e * T_TOK + row_i] >> 1) : -1;
    float4 z4 = make_float4(0.f, 0.f, 0.f, 0.f);
    GEMM_TILE((tok >= 0 ? *(const float4*)&g_xin[(size_t)tok * D_MODEL + k0 + ac] : z4),
              W, D_MODEL, H_HID);
    #pragma unroll
    for (int i = 0; i < 4; i++) {
        int li = m0 + ty * 4 + i;
        if (li >= M) continue;
        int col = n0 + tx * 4;
        const float* bb = b1 + (size_t)e * H_HID;
        float4 o;
        o.x = gelu_tanh(acc[i][0] + bb[col + 0]);
        o.y = gelu_tanh(acc[i][1] + bb[col + 1]);
        o.z = gelu_tanh(acc[i][2] + bb[col + 2]);
        o.w = gelu_tanh(acc[i][3] + bb[col + 3]);
        *(float4*)&g_h1[((size_t)e * T_TOK + li) * H_HID + col] = o;
    }
}

// MoE GEMM2: g_moe2[token,slot] = gate * (h1 @ w2[e] + b2[e])
__global__ void moe_gemm2(const float* __restrict__ w2, const float* __restrict__ b2) {
    int e = blockIdx.z;
    int M = g_cnt[e];
    int m0 = blockIdx.y * 64;
    if (m0 >= M) return;
    int n0 = blockIdx.x * 64;
    const float* W = w2 + (size_t)e * H_HID * D_MODEL;
    const float* Abase = g_h1 + (size_t)e * T_TOK * H_HID;
    GEMM_PROLOG();
    int row_i = m0 + ar;
    bool rv = (row_i < M);
    float4 z4 = make_float4(0.f, 0.f, 0.f, 0.f);
    GEMM_TILE((rv ? *(const float4*)&Abase[(size_t)row_i * H_HID + k0 + ac] : z4),
              W, H_HID, D_MODEL);
    #pragma unroll
    for (int i = 0; i < 4; i++) {
        int li = m0 + ty * 4 + i;
        if (li >= M) continue;
        int pk     = g_list[e * T_TOK + li];
        float gate = g_glist[e * T_TOK + li];
        int col = n0 + tx * 4;
        const float* bb = b2 + (size_t)e * D_MODEL;
        float4 o;
        o.x = gate * (acc[i][0] + bb[col + 0]);
        o.y = gate * (acc[i][1] + bb[col + 1]);
        o.z = gate * (acc[i][2] + bb[col + 2]);
        o.w = gate * (acc[i][3] + bb[col + 3]);
        *(float4*)&g_moe2[(size_t)pk * D_MODEL + col] = o;
    }
}

// ---------------- final combine ----------------
__global__ void combine_kernel(const float* __restrict__ hid,
                               const float* __restrict__ alpha_p,
                               float* __restrict__ out)
{
    int idx = blockIdx.x * blockDim.x + threadIdx.x;   // float4 index over [T,D]
    float a = alpha_p[0];
    int t  = idx >> 7;          // D/4 = 128 float4 per token
    int d4 = idx & 127;
    float4 h  = ((const float4*)hid)[idx];
    float4 s  = ((const float4*)g_sh)[idx];
    float4 m0 = ((const float4*)g_moe2)[(size_t)(2 * t) * 128 + d4];
    float4 m1 = ((const float4*)g_moe2)[(size_t)(2 * t + 1) * 128 + d4];
    float4 o;
    o.x = h.x + s.x + a * (m0.x + m1.x);
    o.y = h.y + s.y + a * (m0.y + m1.y);
    o.z = h.z + s.z + a * (m0.z + m1.z);
    o.w = h.w + s.w + a * (m0.w + m1.w);
    ((float4*)out)[idx] = o;
}

// ---------------- launch -------------------------------------------------------
extern "C" void kernel_launch(void* const* d_in, const int* in_sizes, int n_in,
                              void* d_out, int out_size)
{
    const float* hid    = (const float*)d_in[0];
    const float* raw    = (const float*)d_in[1];
    const float* ln_g   = (const float*)d_in[2];
    const float* ln_b   = (const float*)d_in[3];
    const float* pg     = (const float*)d_in[4];
    const float* pb     = (const float*)d_in[5];
    const float* feat_w = (const float*)d_in[6];
    const float* feat_b = (const float*)d_in[7];
    const float* film_w = (const float*)d_in[8];
    const float* film_b = (const float*)d_in[9];
    const float* rw     = (const float*)d_in[10];
    const float* rb     = (const float*)d_in[11];
    const float* w1     = (const float*)d_in[12];
    const float* b1     = (const float*)d_in[13];
    const float* w2     = (const float*)d_in[14];
    const float* b2     = (const float*)d_in[15];
    const float* fc1    = (const float*)d_in[16];
    const float* fc1b   = (const float*)d_in[17];
    const float* fc2    = (const float*)d_in[18];
    const float* fc2b   = (const float*)d_in[19];
    const float* alpha  = (const float*)d_in[20];
    float* out = (float*)d_out;

    zero_cnt_kernel<<<1, 32>>>();
    prep_kernel<<<T_TOK, 256>>>(hid, raw, ln_g, ln_b, pg, pb,
                                feat_w, feat_b, film_w, film_b, rw, rb);
    ffn_gemm1<<<dim3(DFF_DIM / 64, T_TOK / 64), 256>>>(fc1, fc1b);
    ffn_gemm2<<<dim3(D_MODEL / 64, T_TOK / 64), 256>>>(fc2, fc2b);
    moe_gemm1<<<dim3(H_HID / 64, T_TOK / 64, E_EXP), 256>>>(w1, b1);
    moe_gemm2<<<dim3(D_MODEL / 64, T_TOK / 64, E_EXP), 256>>>(w2, b2);
    combine_kernel<<<(T_TOK * D_MODEL / 4) / 256, 256>>>(hid, alpha, out);
}

// round 4
// speedup vs baseline: 2.0632x; 2.0632x over previous
#include <cuda_runtime.h>
#include <cuda_bf16.h>
#include <math.h>
#include <stdint.h>

#define T_TOK 4096
#define D_MODEL 512
#define E_EXP 8
#define H_HID 1024
#define DFF_DIM 2048

// ---------------- scratch (static device globals; no allocation) --------------
__device__ __align__(16) float g_xin[T_TOK * D_MODEL];
__device__ __align__(16) float g_xs[T_TOK * D_MODEL];
__device__ __align__(16) float g_t1[(size_t)T_TOK * DFF_DIM];
__device__ __align__(16) float g_sh[T_TOK * D_MODEL];
__device__ __align__(16) float g_h1[(size_t)E_EXP * T_TOK * H_HID];
__device__ __align__(16) float g_moe2[T_TOK * 2 * D_MODEL];
__device__ __align__(16) float g_fc1t[(size_t)DFF_DIM * D_MODEL];
__device__ __align__(16) float g_fc2t[(size_t)D_MODEL * DFF_DIM];
__device__ __align__(16) float g_w1t[(size_t)E_EXP * H_HID * D_MODEL];
__device__ __align__(16) float g_w2t[(size_t)E_EXP * D_MODEL * H_HID];
__device__ int   g_cnt[E_EXP];
__device__ int   g_list[E_EXP * T_TOK];
__device__ float g_glist[E_EXP * T_TOK];

__device__ __forceinline__ float gelu_tanh(float x) {
    float x3 = x * x * x;
    return 0.5f * x * (1.0f + tanhf(0.7978845608028654f * (x + 0.044715f * x3)));
}

__device__ __forceinline__ uint32_t smem_u32(const void* p) {
    uint32_t a;
    asm("{ .reg .u64 t; cvta.to.shared.u64 t, %1; cvt.u32.u64 %0, t; }" : "=r"(a) : "l"(p));
    return a;
}

// ---------------- mma.sync helpers (baseline PTX, works on sm_103) -------------
__device__ __forceinline__ void ldmx4(uint32_t* r, uint32_t a) {
    asm volatile("ldmatrix.sync.aligned.m8n8.x4.shared.b16 {%0,%1,%2,%3}, [%4];"
                 : "=r"(r[0]), "=r"(r[1]), "=r"(r[2]), "=r"(r[3]) : "r"(a));
}
__device__ __forceinline__ void mma_bf16(float* c, const uint32_t* a, const uint32_t* b) {
    asm volatile("mma.sync.aligned.m16n8k16.row.col.f32.bf16.bf16.f32 "
                 "{%0,%1,%2,%3}, {%4,%5,%6,%7}, {%8,%9}, {%0,%1,%2,%3};"
                 : "+f"(c[0]), "+f"(c[1]), "+f"(c[2]), "+f"(c[3])
                 : "r"(a[0]), "r"(a[1]), "r"(a[2]), "r"(a[3]), "r"(b[0]), "r"(b[1]));
}

__device__ __forceinline__ uint32_t pk2(float a, float b) {
    __nv_bfloat162 t;
    t.x = __float2bfloat16_rn(a);
    t.y = __float2bfloat16_rn(b);
    return *(uint32_t*)&t;
}

// split a float4 into bf16-hi (packed uint2) and bf16-lo residual (packed uint2)
__device__ __forceinline__ void split4(float4 f, uint2& hi, uint2& lo) {
    float hx = __bfloat162float(__float2bfloat16_rn(f.x));
    float hy = __bfloat162float(__float2bfloat16_rn(f.y));
    float hz = __bfloat162float(__float2bfloat16_rn(f.z));
    float hw = __bfloat162float(__float2bfloat16_rn(f.w));
    hi.x = pk2(hx, hy);             hi.y = pk2(hz, hw);
    lo.x = pk2(f.x - hx, f.y - hy); lo.y = pk2(f.z - hz, f.w - hw);
}

// ---------------- counters reset ----------------------------------------------
__global__ void zero_cnt_kernel() {
    if (threadIdx.x < E_EXP) g_cnt[threadIdx.x] = 0;
}

// ---------------- weight transpose [K][N] -> [N][K] ----------------------------
__global__ void transpose_k(const float* __restrict__ in, float* __restrict__ out,
                            int Kd, int Nd) {
    int b = blockIdx.z;
    in  += (size_t)b * Kd * Nd;
    out += (size_t)b * Kd * Nd;
    __shared__ float t[32][33];
    int k0 = blockIdx.y * 32, n0 = blockIdx.x * 32;
    #pragma unroll
    for (int j = threadIdx.y; j < 32; j += 8)
        t[j][threadIdx.x] = in[(size_t)(k0 + j) * Nd + n0 + threadIdx.x];
    __syncthreads();
    #pragma unroll
    for (int j = threadIdx.y; j < 32; j += 8)
        out[(size_t)(n0 + j) * Kd + k0 + threadIdx.x] = t[threadIdx.x][j];
}

// ---------------- per-token prep: LN x2, feat, FiLM, router top-2 --------------
__global__ void prep_kernel(
    const float* __restrict__ hid, const float* __restrict__ raw,
    const float* __restrict__ ln_g, const float* __restrict__ ln_b,
    const float* __restrict__ pg,   const float* __restrict__ pb,
    const float* __restrict__ feat_w, const float* __restrict__ feat_b,
    const float* __restrict__ film_w, const float* __restrict__ film_b,
    const float* __restrict__ rw, const float* __restrict__ rb)
{
    int t = blockIdx.x;
    int tid = threadIdx.x;

    __shared__ float red[256];
    __shared__ float s_x[D_MODEL];
    __shared__ float s_feat[64];
    __shared__ float s_logits[E_EXP];

    float h0 = hid[t * D_MODEL + tid];
    float h1 = hid[t * D_MODEL + 256 + tid];

    red[tid] = h0 + h1;
    __syncthreads();
    #pragma unroll
    for (int s = 128; s > 0; s >>= 1) {
        if (tid < s) red[tid] += red[tid + s];
        __syncthreads();
    }
    float mean = red[0] * (1.0f / 512.0f);
    __syncthreads();

    float d0 = h0 - mean, d1 = h1 - mean;
    red[tid] = d0 * d0 + d1 * d1;
    __syncthreads();
    #pragma unroll
    for (int s = 128; s > 0; s >>= 1) {
        if (tid < s) red[tid] += red[tid + s];
        __syncthreads();
    }
    float inv = rsqrtf(red[0] * (1.0f / 512.0f) + 1e-5f);

    float x0 = d0 * inv, x1 = d1 * inv;
    s_x[tid]       = x0 * ln_g[tid]       + ln_b[tid];
    s_x[tid + 256] = x1 * ln_g[tid + 256] + ln_b[tid + 256];
    g_xs[t * D_MODEL + tid]       = x0 * pg[tid]       + pb[tid];
    g_xs[t * D_MODEL + tid + 256] = x1 * pg[tid + 256] + pb[tid + 256];

    if (tid < 64) {
        float acc = feat_b[tid];
        #pragma unroll
        for (int i = 0; i < 16; i++) acc += raw[t * 16 + i] * feat_w[i * 64 + tid];
        s_feat[tid] = acc;
    }
    __syncthreads();

    #pragma unroll
    for (int r = 0; r < 2; r++) {
        int d = tid + r * 256;
        float gma = film_b[d];
        float bta = film_b[512 + d];
        #pragma unroll
        for (int i = 0; i < 64; i++) {
            float f = s_feat[i];
            gma += f * film_w[i * 1024 + d];
            bta += f * film_w[i * 1024 + 512 + d];
        }
        g_xin[t * D_MODEL + d] = s_x[d] * (1.0f + gma) + bta;
    }

    {
        int w = tid >> 5, lane = tid & 31;
        float acc = 0.0f;
        #pragma unroll
        for (int d = 0; d < 512; d += 32) acc += s_x[d + lane] * rw[(d + lane) * E_EXP + w];
        #pragma unroll
        for (int off = 16; off; off >>= 1) acc += __shfl_down_sync(0xffffffff, acc, off);
        if (lane == 0) s_logits[w] = acc + rb[w];
    }
    __syncthreads();

    if (tid == 0) {
        int i0 = 0; float v0 = s_logits[0];
        #pragma unroll
        for (int e = 1; e < E_EXP; e++) { float v = s_logits[e]; if (v > v0) { v0 = v; i0 = e; } }
        int i1 = -1; float v1 = -1e30f;
        #pragma unroll
        for (int e = 0; e < E_EXP; e++) {
            if (e == i0) continue;
            float v = s_logits[e]; if (v > v1) { v1 = v; i1 = e; }
        }
        float b  = expf(v1 - v0);
        float g0 = 1.0f / (1.0f + b);
        float g1 = b * g0;
        int p0 = atomicAdd(&g_cnt[i0], 1);
        g_list[i0 * T_TOK + p0] = t * 2 + 0;  g_glist[i0 * T_TOK + p0] = g0;
        int p1 = atomicAdd(&g_cnt[i1], 1);
        g_list[i1 * T_TOK + p1] = t * 2 + 1;  g_glist[i1 * T_TOK + p1] = g1;
    }
}

// ---------------- mma.sync GEMM ------------------------------------------------
// C[128,128] = A[128,K] x Bt[N,K]^T, fp32 via 3-term bf16 split on tensor cores.
// MODE 0: ffn1  A=g_xs   B=g_fc1t  out=gelu(.+b)->g_t1
// MODE 1: ffn2  A=g_t1   B=g_fc2t  out=.+b      ->g_sh
// MODE 2: moe1  A=gather(g_xin)    out=gelu(.+b)->g_h1[e]
// MODE 3: moe2  A=g_h1[e]          out=gate*(.+b)->scatter g_moe2
//
// smem stage layout (per stage, 80B row pitch = 40 bf16):
//   Ah @ +0, Al @ +10240, Bh @ +20480, Bl @ +30720   (stage = 40960 B)
#define STAGE_SZ 40960
#define GSMEM_SZ (1024 + 2 * STAGE_SZ)

template<int MODE, int N, int K>
__global__ void __launch_bounds__(256, 1)
gemm_mma(const float* __restrict__ bias)
{
    constexpr int NC = K / 32;
    const int e = (MODE >= 2) ? blockIdx.z : 0;
    int M = T_TOK;
    if (MODE >= 2) M = g_cnt[e];
    const int m0 = blockIdx.y * 128;
    if (m0 >= M) return;
    const int n0 = blockIdx.x * 128;

    const float* Asrc;
    const float* Bsrc;
    if (MODE == 0) { Asrc = g_xs;  Bsrc = g_fc1t; }
    if (MODE == 1) { Asrc = g_t1;  Bsrc = g_fc2t; }
    if (MODE == 2) { Asrc = g_xin; Bsrc = g_w1t + (size_t)e * N * K; }
    if (MODE == 3) { Asrc = g_h1 + (size_t)e * T_TOK * K; Bsrc = g_w2t + (size_t)e * N * K; }
    const float* bi = bias + ((MODE >= 2) ? e * N : 0);

    extern __shared__ char sm[];
    int* s_tok = (int*)sm;

    const int tid = threadIdx.x;
    const int wid = tid >> 5, lane = tid & 31;
    const int wm = wid & 1, wn = wid >> 1;      // warp tile: rows wm*64..+64, cols wn*32..+32

    if (MODE == 2 && tid < 128) {
        int r = m0 + tid;
        s_tok[tid] = (r < M) ? (g_list[e * T_TOK + r] >> 1) : 0;
    }
    __syncthreads();

    const uint32_t smb = smem_u32(sm);

    float acc[4][4][4];
    #pragma unroll
    for (int i = 0; i < 4; i++)
        #pragma unroll
        for (int j = 0; j < 4; j++)
            #pragma unroll
            for (int q = 0; q < 4; q++) acc[i][j][q] = 0.0f;

    float4 ra[4], rb[4];

    auto ldg_chunk = [&](int c) {
        const int kb = c * 32;
        #pragma unroll
        for (int u = 0; u < 4; u++) {
            int idx = tid + u * 256;
            int row = idx >> 3, c4 = idx & 7;
            const float* pa;
            if (MODE == 2) pa = Asrc + (size_t)s_tok[row] * K + kb + c4 * 4;
            else           pa = Asrc + (size_t)(m0 + row) * K + kb + c4 * 4;
            ra[u] = *(const float4*)pa;
            rb[u] = *(const float4*)(Bsrc + (size_t)(n0 + row) * K + kb + c4 * 4);
        }
    };

    auto sts_chunk = [&](int s) {
        char* st = sm + 1024 + s * STAGE_SZ;
        #pragma unroll
        for (int u = 0; u < 4; u++) {
            int idx = tid + u * 256;
            int row = idx >> 3, c4 = idx & 7;
            uint2 hi, lo;
            split4(ra[u], hi, lo);
            *(uint2*)(st +         row * 80 + c4 * 8) = hi;
            *(uint2*)(st + 10240 + row * 80 + c4 * 8) = lo;
            split4(rb[u], hi, lo);
            *(uint2*)(st + 20480 + row * 80 + c4 * 8) = hi;
            *(uint2*)(st + 30720 + row * 80 + c4 * 8) = lo;
        }
    };

    auto compute = [&](int s) {
        const uint32_t base = smb + 1024 + s * STAGE_SZ;
        #pragma unroll
        for (int ks = 0; ks < 2; ks++) {
            uint32_t ah[4][4], al[4][4], bh[4][2], bl[4][2];
            // A: m16k16 tiles, ldmatrix.x4, addr = row(lane%16), k-half(lane/16)
            uint32_t a_ad = base + ((uint32_t)(wm * 64 + (lane & 15)) * 80u
                                    + (uint32_t)(ks * 16 + (lane >> 4) * 8) * 2u);
            #pragma unroll
            for (int i = 0; i < 4; i++) {
                ldmx4(ah[i], a_ad + i * (16 * 80));
                ldmx4(al[i], a_ad + 10240 + i * (16 * 80));
            }
            // B: two j-tiles per ldmatrix.x4 (matrices = (j,khalf) pairs)
            uint32_t b_ad = base + 20480
                + ((uint32_t)(wn * 32 + (lane >> 4) * 8 + (lane & 7)) * 80u
                   + (uint32_t)(ks * 16 + ((lane >> 3) & 1) * 8) * 2u);
            #pragma unroll
            for (int jj = 0; jj < 2; jj++) {
                uint32_t r[4];
                ldmx4(r, b_ad + jj * (16 * 80));
                bh[jj * 2][0] = r[0]; bh[jj * 2][1] = r[1];
                bh[jj * 2 + 1][0] = r[2]; bh[jj * 2 + 1][1] = r[3];
                ldmx4(r, b_ad + 10240 + jj * (16 * 80));
                bl[jj * 2][0] = r[0]; bl[jj * 2][1] = r[1];
                bl[jj * 2 + 1][0] = r[2]; bl[jj * 2 + 1][1] = r[3];
            }
            #pragma unroll
            for (int i = 0; i < 4; i++)
                #pragma unroll
                for (int j = 0; j < 4; j++) {
                    mma_bf16(acc[i][j], ah[i], bh[j]);
                    mma_bf16(acc[i][j], ah[i], bl[j]);
                    mma_bf16(acc[i][j], al[i], bh[j]);
                }
        }
    };

    ldg_chunk(0);
    sts_chunk(0);
    __syncthreads();

    #pragma unroll 1
    for (int c = 0; c < NC; c++) {
        if (c + 1 < NC) ldg_chunk(c + 1);     // LDGs in flight during compute
        compute(c & 1);
        if (c + 1 < NC) sts_chunk((c + 1) & 1);
        __syncthreads();
    }

    // ---- epilogue: bias / act / gate, direct float2 stores ----
    #pragma unroll
    for (int i = 0; i < 4; i++) {
        #pragma unroll
        for (int half = 0; half < 2; half++) {
            int lr = wm * 64 + i * 16 + (lane >> 2) + half * 8;
            int gr = m0 + lr;
            if (MODE >= 2 && gr >= M) continue;
            float gate = 1.0f;
            int orow = gr;
            if (MODE == 3) {
                gate = g_glist[e * T_TOK + gr];
                orow = g_list[e * T_TOK + gr];
            }
            #pragma unroll
            for (int j = 0; j < 4; j++) {
                int col = wn * 32 + j * 8 + (lane & 3) * 2;
                float v0 = acc[i][j][half * 2 + 0] + bi[n0 + col];
                float v1 = acc[i][j][half * 2 + 1] + bi[n0 + col + 1];
                if (MODE == 0 || MODE == 2) { v0 = gelu_tanh(v0); v1 = gelu_tanh(v1); }
                if (MODE == 3) { v0 *= gate; v1 *= gate; }
                float2 v = make_float2(v0, v1);
                if (MODE == 0) *(float2*)&g_t1[(size_t)gr * DFF_DIM + n0 + col] = v;
                if (MODE == 1) *(float2*)&g_sh[(size_t)gr * D_MODEL + n0 + col] = v;
                if (MODE == 2) *(float2*)&g_h1[((size_t)e * T_TOK + gr) * H_HID + n0 + col] = v;
                if (MODE == 3) *(float2*)&g_moe2[(size_t)orow * D_MODEL + n0 + col] = v;
            }
        }
    }
}

// ---------------- final combine ----------------
__global__ void combine_kernel(const float* __restrict__ hid,
                               const float* __restrict__ alpha_p,
                               float* __restrict__ out)
{
    int idx = blockIdx.x * blockDim.x + threadIdx.x;
    float a = alpha_p[0];
    int t  = idx >> 7;
    int d4 = idx & 127;
    float4 h  = ((const float4*)hid)[idx];
    float4 s  = ((const float4*)g_sh)[idx];
    float4 m0 = ((const float4*)g_moe2)[(size_t)(2 * t) * 128 + d4];
    float4 m1 = ((const float4*)g_moe2)[(size_t)(2 * t + 1) * 128 + d4];
    float4 o;
    o.x = h.x + s.x + a * (m0.x + m1.x);
    o.y = h.y + s.y + a * (m0.y + m1.y);
    o.z = h.z + s.z + a * (m0.z + m1.z);
    o.w = h.w + s.w + a * (m0.w + m1.w);
    ((float4*)out)[idx] = o;
}

// ---------------- launch -------------------------------------------------------
extern "C" void kernel_launch(void* const* d_in, const int* in_sizes, int n_in,
                              void* d_out, int out_size)
{
    const float* hid    = (const float*)d_in[0];
    const float* raw    = (const float*)d_in[1];
    const float* ln_g   = (const float*)d_in[2];
    const float* ln_b   = (const float*)d_in[3];
    const float* pg     = (const float*)d_in[4];
    const float* pb     = (const float*)d_in[5];
    const float* feat_w = (const float*)d_in[6];
    const float* feat_b = (const float*)d_in[7];
    const float* film_w = (const float*)d_in[8];
    const float* film_b = (const float*)d_in[9];
    const float* rw     = (const float*)d_in[10];
    const float* rb     = (const float*)d_in[11];
    const float* w1     = (const float*)d_in[12];
    const float* b1     = (const float*)d_in[13];
    const float* w2     = (const float*)d_in[14];
    const float* b2     = (const float*)d_in[15];
    const float* fc1    = (const float*)d_in[16];
    const float* fc1b   = (const float*)d_in[17];
    const float* fc2    = (const float*)d_in[18];
    const float* fc2b   = (const float*)d_in[19];
    const float* alpha  = (const float*)d_in[20];
    float* out = (float*)d_out;

    cudaFuncSetAttribute(gemm_mma<0, DFF_DIM, D_MODEL>, cudaFuncAttributeMaxDynamicSharedMemorySize, GSMEM_SZ);
    cudaFuncSetAttribute(gemm_mma<1, D_MODEL, DFF_DIM>, cudaFuncAttributeMaxDynamicSharedMemorySize, GSMEM_SZ);
    cudaFuncSetAttribute(gemm_mma<2, H_HID,  D_MODEL>, cudaFuncAttributeMaxDynamicSharedMemorySize, GSMEM_SZ);
    cudaFuncSetAttribute(gemm_mma<3, D_MODEL, H_HID >, cudaFuncAttributeMaxDynamicSharedMemorySize, GSMEM_SZ);

    float *fc1t_p, *fc2t_p, *w1t_p, *w2t_p;
    cudaGetSymbolAddress((void**)&fc1t_p, g_fc1t);
    cudaGetSymbolAddress((void**)&fc2t_p, g_fc2t);
    cudaGetSymbolAddress((void**)&w1t_p,  g_w1t);
    cudaGetSymbolAddress((void**)&w2t_p,  g_w2t);

    zero_cnt_kernel<<<1, 32>>>();
    transpose_k<<<dim3(DFF_DIM / 32, D_MODEL / 32, 1), dim3(32, 8)>>>(fc1, fc1t_p, D_MODEL, DFF_DIM);
    transpose_k<<<dim3(D_MODEL / 32, DFF_DIM / 32, 1), dim3(32, 8)>>>(fc2, fc2t_p, DFF_DIM, D_MODEL);
    transpose_k<<<dim3(H_HID / 32,  D_MODEL / 32, E_EXP), dim3(32, 8)>>>(w1, w1t_p, D_MODEL, H_HID);
    transpose_k<<<dim3(D_MODEL / 32, H_HID / 32,  E_EXP), dim3(32, 8)>>>(w2, w2t_p, H_HID, D_MODEL);
    prep_kernel<<<T_TOK, 256>>>(hid, raw, ln_g, ln_b, pg, pb,
                                feat_w, feat_b, film_w, film_b, rw, rb);
    gemm_mma<0, DFF_DIM, D_MODEL><<<dim3(DFF_DIM / 128, T_TOK / 128), 256, GSMEM_SZ>>>(fc1b);
    gemm_mma<1, D_MODEL, DFF_DIM><<<dim3(D_MODEL / 128, T_TOK / 128), 256, GSMEM_SZ>>>(fc2b);
    gemm_mma<2, H_HID,  D_MODEL><<<dim3(H_HID / 128,  T_TOK / 128, E_EXP), 256, GSMEM_SZ>>>(b1);
    gemm_mma<3, D_MODEL, H_HID ><<<dim3(D_MODEL / 128, T_TOK / 128, E_EXP), 256, GSMEM_SZ>>>(b2);
    combine_kernel<<<(T_TOK * D_MODEL / 4) / 256, 256>>>(hid, alpha, out);
}